// round 3
// baseline (speedup 1.0000x reference)
#include <cuda_runtime.h>
#include <math.h>

// MaskAlignmentLoss fused single-kernel version.
// B=4, N=6890, H=W=64. One launch: compact -> global barrier -> pairwise mins
// -> sqrt -> block reduce -> atomicAdd into out.

#define BATCH  4
#define NV     6890
#define HW     4096
#define INF2   1.0e18f
#define NB_P1  128                 // pass1 blocks: 32 per batch, 64 pixels each
#define NB_P2  108                 // pass2 blocks: 256 verts each (27648 >= 27560)
#define NBLK   (NB_P1 + NB_P2)     // 236 (<= 148 * min-occupancy, all co-resident)
#define CHUNK  2048                // candidate slots staged per smem chunk
#define NVSLOT ((NV + 1) / 2)      // 3445 packed vert slots
#define SENT   (-1.0e9f)

// -------- persistent device state --------
__device__ __align__(16) float2 g_pts[BATCH][HW];  // compacted normalized pixels
__device__ int      g_cnt[BATCH];
__device__ unsigned g_arrive;                      // monotonic barrier counter

// -------- packed f32x2 helpers (sm_103a) --------
typedef unsigned long long u64;
__device__ __forceinline__ u64 pk(float a, float b) {
    u64 r; asm("mov.b64 %0, {%1, %2};" : "=l"(r) : "f"(a), "f"(b)); return r;
}
__device__ __forceinline__ void upk(u64 v, float& a, float& b) {
    asm("mov.b64 {%0, %1}, %2;" : "=f"(a), "=f"(b) : "l"(v));
}
__device__ __forceinline__ u64 add2(u64 a, u64 b) {
    u64 r; asm("add.rn.f32x2 %0, %1, %2;" : "=l"(r) : "l"(a), "l"(b)); return r;
}
__device__ __forceinline__ u64 mul2(u64 a, u64 b) {
    u64 r; asm("mul.rn.f32x2 %0, %1, %2;" : "=l"(r) : "l"(a), "l"(b)); return r;
}
__device__ __forceinline__ u64 fma2(u64 a, u64 b, u64 c) {
    u64 r; asm("fma.rn.f32x2 %0, %1, %2, %3;" : "=l"(r) : "l"(a), "l"(b), "l"(c)); return r;
}
__device__ __forceinline__ float sqrt_ap(float x) {
    float r; asm("sqrt.approx.f32 %0, %1;" : "=f"(r) : "f"(x)); return r;
}

__global__ void __launch_bounds__(256) k_fused(const float* __restrict__ vert,
                                               const int*   __restrict__ mask,
                                               float*       __restrict__ out) {
    __shared__ float4 sXY[CHUNK];     // 32 KB candidate staging
    __shared__ float  red[256];
    __shared__ int    wtot[8], woff[8];

    const int bx = blockIdx.x;
    const int tid = threadIdx.x;

    // ================= phase A: setup =================
    if (bx < BATCH) {
        // compact valid pixels of batch bx (coalesced int4 loads)
        const int b = bx;
        const int4* m4 = (const int4*)(mask + b * HW);
        unsigned vb[4]; int c = 0;
#pragma unroll
        for (int r = 0; r < 4; r++) {
            int4 v = m4[tid + r * 256];
            unsigned bits = (v.x > 0 ? 1u : 0u) | (v.y > 0 ? 2u : 0u) |
                            (v.z > 0 ? 4u : 0u) | (v.w > 0 ? 8u : 0u);
            vb[r] = bits;
            c += __popc(bits);
        }
        int lane = tid & 31, wid = tid >> 5;
        int incl = c;
#pragma unroll
        for (int d = 1; d < 32; d <<= 1) {
            int t = __shfl_up_sync(0xffffffffu, incl, d);
            if (lane >= d) incl += t;
        }
        if (lane == 31) wtot[wid] = incl;
        __syncthreads();
        if (tid < 8) {
            int v = wtot[tid], s = v;
#pragma unroll
            for (int d = 1; d < 8; d <<= 1) {
                int t = __shfl_up_sync(0xffu, s, d);
                if (tid >= d) s += t;
            }
            woff[tid] = s - v;
            if (tid == 7) g_cnt[b] = s;
        }
        __syncthreads();
        int off = woff[wid] + (incl - c);
#pragma unroll
        for (int r = 0; r < 4; r++) {
            unsigned bits = vb[r];
            int pbase = (tid + r * 256) * 4;
#pragma unroll
            for (int k = 0; k < 4; k++) {
                if ((bits >> k) & 1u) {
                    int p = pbase + k;
                    g_pts[b][off++] = make_float2((float)(p & 63) * (1.0f / 64.0f),
                                                  (float)(p >> 6) * (1.0f / 64.0f));
                }
            }
        }
    }
    if (bx == BATCH && tid == 0) out[0] = 0.0f;

    // ================= global barrier (monotonic, replay-safe) =================
    __syncthreads();
    if (tid == 0) {
        __threadfence();
        unsigned t = atomicAdd(&g_arrive, 1u);
        unsigned target = t - (t % (unsigned)NBLK) + (unsigned)NBLK;
        while (*(volatile unsigned*)&g_arrive < target) { __nanosleep(64); }
    }
    __syncthreads();

    // ================= phase B: pairwise mins =================
    float sum_local = 0.0f;

    if (bx < NB_P1) {
        // ---- pass1: per valid pixel, min over all verts (4 threads/pixel) ----
        const int b   = bx >> 5;        // 32 blocks per batch
        const int blk = bx & 31;
        const int cnt = g_cnt[b];
        const float4* vb4 = (const float4*)(vert + (size_t)b * NV * 2);
        const int q = tid & 3, lane_pix = tid >> 2;   // quarter, pixel-in-block

        for (int i0 = blk * 64; i0 < cnt; i0 += 32 * 64) {
            int i = i0 + lane_pix;
            bool act = (i < cnt);
            float px = 0.f, py = 0.f;
            if (act) { float2 p = g_pts[b][i]; px = p.x; py = p.y; }
            u64 PX = pk(px, px), PY = pk(py, py);

            float mn0 = INF2, mn1 = INF2;
            for (int c0 = 0; c0 < NVSLOT; c0 += CHUNK) {
                int clen = min(CHUNK, NVSLOT - c0);
                __syncthreads();
                for (int j = tid; j < clen; j += 256) {
                    float4 v = vb4[c0 + j];       // (x0,y0,x1,y1) of 2 verts
                    sXY[j] = make_float4(v.x * (-1.0f / 64.0f), v.z * (-1.0f / 64.0f),
                                         v.y * (-1.0f / 64.0f), v.w * (-1.0f / 64.0f));
                }
                __syncthreads();
                // quarter stride, adjusted so the 4 groups hit distinct banks
                int qlen = (clen + 3) >> 2;
                if (qlen & 1) qlen++;
                int m8 = qlen & 7;
                if (m8 == 0 || m8 == 4) qlen += 2;
                int jb = q * qlen, je = min(jb + qlen, clen);
#pragma unroll 4
                for (int j = jb; j < je; j++) {
                    float4 w = sXY[j];
                    u64 dX = add2(PX, pk(w.x, w.y));
                    u64 dY = add2(PY, pk(w.z, w.w));
                    u64 D  = fma2(dX, dX, mul2(dY, dY));
                    float lo, hi; upk(D, lo, hi);
                    mn0 = fminf(mn0, lo);
                    mn1 = fminf(mn1, hi);
                }
            }
            float mn = fminf(mn0, mn1);
            mn = fminf(mn, __shfl_xor_sync(0xffffffffu, mn, 1));
            mn = fminf(mn, __shfl_xor_sync(0xffffffffu, mn, 2));
            if (act && q == 0) sum_local += sqrt_ap(mn);
        }
    } else {
        // ---- pass2: per vert, min over all valid pixels (1 thread/vert) ----
        const int gblk = (bx - NB_P1) * 256;
        const int g0 = gblk + tid;
        const int b_lo = gblk / NV;
        const int b_hi = min((gblk + 255) / NV, BATCH - 1);

        bool act = (g0 < BATCH * NV);
        int myb = act ? (g0 / NV) : -1;
        float vx = 0.f, vy = 0.f;
        if (act) {
            float2 v = *(const float2*)(vert + (size_t)g0 * 2);
            vx = v.x * (1.0f / 64.0f);
            vy = v.y * (1.0f / 64.0f);
        }
        u64 VX = pk(vx, vx), VY = pk(vy, vy);

        float best = INF2;
        for (int b = b_lo; b <= b_hi; b++) {
            int cnt = g_cnt[b];
            int ns = (cnt + 1) >> 1;
            __syncthreads();
            for (int j = tid; j < ns; j += 256) {
                float4 pp = *(const float4*)&g_pts[b][2 * j];
                float x1 = SENT, y1 = SENT;
                if (2 * j + 1 < cnt) { x1 = -pp.z; y1 = -pp.w; }
                sXY[j] = make_float4(-pp.x, x1, -pp.y, y1);
            }
            __syncthreads();
            if (myb == b) {
                float mn0 = INF2, mn1 = INF2;
#pragma unroll 4
                for (int j = 0; j < ns; j++) {
                    float4 w = sXY[j];
                    u64 dX = add2(VX, pk(w.x, w.y));
                    u64 dY = add2(VY, pk(w.z, w.w));
                    u64 D  = fma2(dX, dX, mul2(dY, dY));
                    float lo, hi; upk(D, lo, hi);
                    mn0 = fminf(mn0, lo);
                    mn1 = fminf(mn1, hi);
                }
                best = fminf(mn0, mn1);
            }
        }
        if (act) sum_local += sqrt_ap(best);   // cnt==0 -> INF2 -> 1e9 == BIG
    }

    // ================= phase C: block reduce + atomicAdd =================
    __syncthreads();
    red[tid] = sum_local;
    __syncthreads();
#pragma unroll
    for (int d = 128; d > 0; d >>= 1) {
        if (tid < d) red[tid] += red[tid + d];
        __syncthreads();
    }
    if (tid == 0) atomicAdd(out, red[0]);
}

extern "C" void kernel_launch(void* const* d_in, const int* in_sizes, int n_in,
                              void* d_out, int out_size) {
    const float* vert2d = (const float*)d_in[0];   // [B, N, 2] float32
    const int*   mask   = (const int*)d_in[1];     // [B, H, W] int32
    float* out = (float*)d_out;
    (void)in_sizes; (void)n_in; (void)out_size;

    k_fused<<<NBLK, 256>>>(vert2d, mask, out);
}

// round 4
// speedup vs baseline: 2.6931x; 2.6931x over previous
#include <cuda_runtime.h>
#include <math.h>

// MaskAlignmentLoss via exact grid-accelerated nearest-neighbor search.
// B=4, N=6890, H=W=64. Distances in raw pixel units, scaled 1/64 per term.

#define BATCH 4
#define NV    6890
#define HW    4096
#define INF2  1.0e18f
#define INV64 0.015625f
#define NB_A  64                      // pixel-query blocks (4 batches x 16)
#define NB_B  108                     // vert-query blocks (27648 >= 27560)
#define BIGF  1.0e9f

// -------- device scratch --------
__device__ unsigned g_mbits[BATCH][128];          // mask bitset, bit p = pixel y*64+x
__device__ unsigned g_binpack[BATCH][4096];       // per vert-bin: off | (cnt<<16)
__device__ __align__(8) float2 g_vsort[BATCH][NV]; // verts grouped by bin (pixel units)

__device__ __forceinline__ float sqrt_ap(float x) {
    float r; asm("sqrt.approx.f32 %0, %1;" : "=f"(r) : "f"(x)); return r;
}

// ================= kernel 1: per-batch preprocessing (4 blocks) =================
__global__ void __launch_bounds__(256) k_prep(const float* __restrict__ vert,
                                              const int*   __restrict__ mask,
                                              float*       __restrict__ out) {
    __shared__ unsigned cursor[4096];   // counts -> offsets -> scatter cursors
    __shared__ unsigned mwords[128];
    __shared__ unsigned wtot[8];

    const int b = blockIdx.x, tid = threadIdx.x;

    if (tid < 128) mwords[tid] = 0;
#pragma unroll
    for (int k = 0; k < 16; k++) cursor[tid * 16 + k] = 0;
    __syncthreads();

    // ---- mask bitset (coalesced int4 loads) ----
    const int4* m4 = (const int4*)(mask + b * HW);
#pragma unroll
    for (int r = 0; r < 4; r++) {
        int idx = tid + r * 256;                  // int4 index; pixels 4*idx..4*idx+3
        int4 v = m4[idx];
        unsigned bits = (v.x > 0 ? 1u : 0u) | (v.y > 0 ? 2u : 0u) |
                        (v.z > 0 ? 4u : 0u) | (v.w > 0 ? 8u : 0u);
        if (bits) atomicOr(&mwords[idx >> 3], bits << ((idx & 7) * 4));
    }

    // ---- vert bin counts (64x64 bins == pixel cells) ----
    const float2* vb = (const float2*)(vert + (size_t)b * NV * 2);
    for (int i = tid; i < NV; i += 256) {
        float2 v = vb[i];
        int ix = min(63, (int)v.x), iy = min(63, (int)v.y);
        atomicAdd(&cursor[iy * 64 + ix], 1u);
    }
    __syncthreads();

    if (tid < 128) g_mbits[b][tid] = mwords[tid];

    // ---- block-wide exclusive scan over 4096 counts (16/thread) ----
    unsigned c[16], tsum = 0;
#pragma unroll
    for (int k = 0; k < 16; k++) { c[k] = cursor[tid * 16 + k]; tsum += c[k]; }
    int lane = tid & 31, wid = tid >> 5;
    unsigned incl = tsum;
#pragma unroll
    for (int d = 1; d < 32; d <<= 1) {
        unsigned t = __shfl_up_sync(0xffffffffu, incl, d);
        if (lane >= d) incl += t;
    }
    if (lane == 31) wtot[wid] = incl;
    __syncthreads();
    unsigned base = incl - tsum;
    for (int w = 0; w < wid; w++) base += wtot[w];
    unsigned run = base;
#pragma unroll
    for (int k = 0; k < 16; k++) {
        g_binpack[b][tid * 16 + k] = run | (c[k] << 16);
        cursor[tid * 16 + k] = run;
        run += c[k];
    }
    __syncthreads();

    // ---- scatter verts by bin ----
    for (int i = tid; i < NV; i += 256) {
        float2 v = vb[i];
        int ix = min(63, (int)v.x), iy = min(63, (int)v.y);
        unsigned slot = atomicAdd(&cursor[iy * 64 + ix], 1u);
        g_vsort[b][slot] = v;
    }

    if (b == 0 && tid == 0) out[0] = 0.0f;
}

// ================= kernel 2: ring searches + reduce (172 blocks) =================
__global__ void __launch_bounds__(256) k_search(const float* __restrict__ vert,
                                                float* __restrict__ out) {
    __shared__ unsigned sbits[512];
    __shared__ float red[256];
    const int bx = blockIdx.x, tid = threadIdx.x;
    float s = 0.0f;

    if (bx < NB_A) {
        // ---------- pixel -> nearest vert ----------
        const int b = bx >> 4;
        if (tid < 128) sbits[tid] = g_mbits[b][tid];
        __syncthreads();

        int p = (bx & 15) * 256 + tid;
        if ((sbits[p >> 5] >> (p & 31)) & 1u) {
            int cx = p & 63, cy = p >> 6;
            float px = (float)cx, py = (float)cy;
            float best = INF2;
            const unsigned* bp = g_binpack[b];
            const float2*   vs = g_vsort[b];

#define EVAL_VBIN(X, Y) do {                                           \
        unsigned pk = bp[(Y) * 64 + (X)];                              \
        int off = pk & 0xFFFF, n = pk >> 16;                           \
        for (int k = 0; k < n; k++) {                                  \
            float2 w = vs[off + k];                                    \
            float dx = px - w.x, dy = py - w.y;                        \
            best = fminf(best, fmaf(dx, dx, dy * dy));                 \
        } } while (0)

            for (int r = 0; r <= 63; r++) {
                if (r > 0) {
                    float lb = (float)((r - 1) * (r - 1));
                    if (best <= lb) break;
                }
                int x0 = max(cx - r, 0), x1 = min(cx + r, 63);
                int yt = cy - r;
                if (yt >= 0) for (int x = x0; x <= x1; x++) EVAL_VBIN(x, yt);
                if (r > 0) {
                    int yb = cy + r;
                    if (yb <= 63) for (int x = x0; x <= x1; x++) EVAL_VBIN(x, yb);
                    int yy0 = max(cy - r + 1, 0), yy1 = min(cy + r - 1, 63);
                    int xl = cx - r, xr = cx + r;
                    if (xl >= 0) for (int y = yy0; y <= yy1; y++) EVAL_VBIN(xl, y);
                    if (xr <= 63) for (int y = yy0; y <= yy1; y++) EVAL_VBIN(xr, y);
                }
            }
            s = sqrt_ap(best) * INV64;
        }
    } else {
        // ---------- vert -> nearest valid pixel ----------
#pragma unroll
        for (int k = 0; k < 2; k++) sbits[tid + k * 256] = ((const unsigned*)g_mbits)[tid + k * 256];
        __syncthreads();

        int g = (bx - NB_A) * 256 + tid;
        if (g < BATCH * NV) {
            int b = g / NV;
            float2 v = *(const float2*)(vert + (size_t)g * 2);
            float vx = v.x, vy = v.y;
            int cx = min(63, (int)vx), cy = min(63, (int)vy);
            const unsigned* mb = &sbits[b * 128];
            float best = INF2;

#define EVAL_PIX(X, Y) do {                                            \
        int q = (Y) * 64 + (X);                                        \
        if ((mb[q >> 5] >> (q & 31)) & 1u) {                           \
            float dx = vx - (float)(X), dy = vy - (float)(Y);          \
            best = fminf(best, fmaf(dx, dx, dy * dy));                 \
        } } while (0)

            for (int r = 0; r <= 63; r++) {
                if (r > 0) {
                    float lb = (float)((r - 1) * (r - 1));
                    if (best <= lb) break;
                }
                int x0 = max(cx - r, 0), x1 = min(cx + r, 63);
                int yt = cy - r;
                if (yt >= 0) for (int x = x0; x <= x1; x++) EVAL_PIX(x, yt);
                if (r > 0) {
                    int yb = cy + r;
                    if (yb <= 63) for (int x = x0; x <= x1; x++) EVAL_PIX(x, yb);
                    int yy0 = max(cy - r + 1, 0), yy1 = min(cy + r - 1, 63);
                    int xl = cx - r, xr = cx + r;
                    if (xl >= 0) for (int y = yy0; y <= yy1; y++) EVAL_PIX(xl, y);
                    if (xr <= 63) for (int y = yy0; y <= yy1; y++) EVAL_PIX(xr, y);
                }
            }
            s = (best >= 1.0e17f) ? BIGF : sqrt_ap(best) * INV64;  // empty mask -> BIG
        }
    }

    // ---------- block reduce + atomicAdd ----------
    __syncthreads();
    red[tid] = s;
    __syncthreads();
#pragma unroll
    for (int d = 128; d > 0; d >>= 1) {
        if (tid < d) red[tid] += red[tid + d];
        __syncthreads();
    }
    if (tid == 0) atomicAdd(out, red[0]);
}

extern "C" void kernel_launch(void* const* d_in, const int* in_sizes, int n_in,
                              void* d_out, int out_size) {
    const float* vert2d = (const float*)d_in[0];   // [B, N, 2] float32, pixel units
    const int*   mask   = (const int*)d_in[1];     // [B, H, W] int32
    float* out = (float*)d_out;
    (void)in_sizes; (void)n_in; (void)out_size;

    k_prep<<<BATCH, 256>>>(vert2d, mask, out);
    k_search<<<NB_A + NB_B, 256>>>(vert2d, out);
}